// round 9
// baseline (speedup 1.0000x reference)
#include <cuda_runtime.h>

// FDTD 2-step update (Ampere + Faraday with 3rd-order one-sided boundary stencils)
// B=8, E:1024x1024, Hx:1022x1023, Hy:1023x1022.
// Outputs (concat along axis 1): E:(8,2048,1024)  Hx:(8,2044,1023)  Hy:(8,2046,1022)
// DT/DX = DT/(Z*DY) = 0.5 ; cf = [-11/6, 3, -3/2, 1/3]

#define CF0 (-11.0f/6.0f)
#define CF1 ( 3.0f)
#define CF2 (-1.5f)
#define CF3 ( 1.0f/3.0f)

// ---------------------------------------------------------------------------
// Ampere: E_n[i,j] = E[i,j] + S1 - S2  on 1024x1024
// ---------------------------------------------------------------------------
template<bool FAST>
__device__ __forceinline__ float amper_pt(
    const float* __restrict__ E, const float* __restrict__ Hx,
    const float* __restrict__ Hy, const float fl[12], int i, int j)
{
    float s = __ldg(E + i*1024 + j);

    // 2D conv terms (Hy with f^T, Hx with f), valid region rows/cols [2,1021]
    if (FAST || (i >= 2 && i <= 1021 && j >= 2 && j <= 1021)) {
        float a1 = 0.f;
        #pragma unroll
        for (int a = 0; a < 4; a++)
            #pragma unroll
            for (int b = 0; b < 3; b++)
                a1 = fmaf(__ldg(Hy + (i-2+a)*1022 + (j-2+b)), fl[b*4+a], a1);
        float a2 = 0.f;
        #pragma unroll
        for (int a = 0; a < 3; a++)
            #pragma unroll
            for (int b = 0; b < 4; b++)
                a2 = fmaf(__ldg(Hx + (i-2+a)*1023 + (j-2+b)), fl[a*4+b], a2);
        s += 0.5f * (a1 - a2);
    }
    // S1 forward vertical (Hy), rows [0,1019], cols [1,1022]
    if (FAST || (i <= 1019 && j >= 1 && j <= 1022)) {
        const float* p = Hy + i*1022 + (j-1);
        s += 0.5f*(CF0*__ldg(p) + CF1*__ldg(p+1022) + CF2*__ldg(p+2044) + CF3*__ldg(p+3066));
    }
    // S1 backward vertical (Hy), rows [4,1023], cols [1,1022]
    if (FAST || (i >= 4 && j >= 1 && j <= 1022)) {
        const float* p = Hy + (i-4)*1022 + (j-1);
        s -= 0.5f*(CF3*__ldg(p) + CF2*__ldg(p+1022) + CF1*__ldg(p+2044) + CF0*__ldg(p+3066));
    }
    // S2 forward horizontal (Hx), rows [1,1022], cols [0,1019]   (enters with minus)
    if (FAST || (i >= 1 && i <= 1022 && j <= 1019)) {
        const float* p = Hx + (i-1)*1023 + j;
        s -= 0.5f*(CF0*__ldg(p) + CF1*__ldg(p+1) + CF2*__ldg(p+2) + CF3*__ldg(p+3));
    }
    // S2 backward horizontal (Hx), rows [1,1022], cols [4,1023]  (minus of minus)
    if (FAST || (i >= 1 && i <= 1022 && j >= 4)) {
        const float* p = Hx + (i-1)*1023 + (j-4);
        s += 0.5f*(CF3*__ldg(p) + CF2*__ldg(p+1) + CF1*__ldg(p+2) + CF0*__ldg(p+3));
    }
    return s;
}

__global__ __launch_bounds__(256)
void amper_kernel(const float* __restrict__ E,  int Es,
                  const float* __restrict__ Hx, int Hxs,
                  const float* __restrict__ Hy, int Hys,
                  const float* __restrict__ F,
                  float* __restrict__ Eout, int Eos)
{
    int b = blockIdx.z;
    E    += (size_t)b * Es;
    Hx   += (size_t)b * Hxs;
    Hy   += (size_t)b * Hys;
    Eout += (size_t)b * Eos;

    float fl[12];
    #pragma unroll
    for (int k = 0; k < 12; k++) fl[k] = __ldg(F + k);

    int i  = blockIdx.y * blockDim.y + threadIdx.y;          // 0..1023
    int j0 = (blockIdx.x * blockDim.x + threadIdx.x) * 4;    // 0..1020

    if (i >= 4 && i <= 1019 && j0 >= 4 && j0 <= 1016) {
        float4 v;
        v.x = amper_pt<true>(E, Hx, Hy, fl, i, j0 + 0);
        v.y = amper_pt<true>(E, Hx, Hy, fl, i, j0 + 1);
        v.z = amper_pt<true>(E, Hx, Hy, fl, i, j0 + 2);
        v.w = amper_pt<true>(E, Hx, Hy, fl, i, j0 + 3);
        *reinterpret_cast<float4*>(Eout + i*1024 + j0) = v;
    } else {
        #pragma unroll
        for (int u = 0; u < 4; u++)
            Eout[i*1024 + j0 + u] = amper_pt<false>(E, Hx, Hy, fl, i, j0 + u);
    }
}

// ---------------------------------------------------------------------------
// Faraday: Hx_n = Hx - S3 (1022x1023) ;  Hy_n = Hy + S4 (1023x1022)
// ---------------------------------------------------------------------------
template<bool FAST>
__device__ __forceinline__ float hx_pt(
    const float* __restrict__ E, const float* __restrict__ Hx,
    const float fl[12], int i, int j)
{
    float s3 = 0.f;
    // conv(E,f) padded cols (1,1): cols [1,1021]
    if (FAST || (j >= 1 && j <= 1021)) {
        float a = 0.f;
        #pragma unroll
        for (int a2 = 0; a2 < 3; a2++)
            #pragma unroll
            for (int b = 0; b < 4; b++)
                a = fmaf(__ldg(E + (i+a2)*1024 + (j-1+b)), fl[a2*4+b], a);
        s3 += 0.5f * a;
    }
    // forward horizontal on E row i+1, cols [0,1020]
    if (FAST || j <= 1020) {
        const float* p = E + (i+1)*1024 + j;
        s3 += 0.5f*(CF0*__ldg(p) + CF1*__ldg(p+1) + CF2*__ldg(p+2) + CF3*__ldg(p+3));
    }
    // backward horizontal on E row i+1, cols [2,1022]
    if (FAST || j >= 2) {
        const float* p = E + (i+1)*1024 + (j-2);
        s3 -= 0.5f*(CF3*__ldg(p) + CF2*__ldg(p+1) + CF1*__ldg(p+2) + CF0*__ldg(p+3));
    }
    return __ldg(Hx + i*1023 + j) - s3;
}

template<bool FAST>
__device__ __forceinline__ float hy_pt(
    const float* __restrict__ E, const float* __restrict__ Hy,
    const float fl[12], int i, int j)
{
    float s4 = 0.f;
    // conv(E,f^T) padded rows (1,1): rows [1,1021]
    if (FAST || (i >= 1 && i <= 1021)) {
        float a = 0.f;
        #pragma unroll
        for (int a2 = 0; a2 < 4; a2++)
            #pragma unroll
            for (int b = 0; b < 3; b++)
                a = fmaf(__ldg(E + (i-1+a2)*1024 + (j+b)), fl[b*4+a2], a);
        s4 += 0.5f * a;
    }
    // forward vertical on E col j+1, rows [0,1020]
    if (FAST || i <= 1020) {
        const float* p = E + i*1024 + (j+1);
        s4 += 0.5f*(CF0*__ldg(p) + CF1*__ldg(p+1024) + CF2*__ldg(p+2048) + CF3*__ldg(p+3072));
    }
    // backward vertical on E col j+1, rows [2,1022]
    if (FAST || i >= 2) {
        const float* p = E + (i-2)*1024 + (j+1);
        s4 -= 0.5f*(CF3*__ldg(p) + CF2*__ldg(p+1024) + CF1*__ldg(p+2048) + CF0*__ldg(p+3072));
    }
    return __ldg(Hy + i*1022 + j) + s4;
}

__global__ __launch_bounds__(256)
void faraday_kernel(const float* __restrict__ E,  int Es,
                    const float* __restrict__ Hx, int Hxs,
                    const float* __restrict__ Hy, int Hys,
                    const float* __restrict__ F,
                    float* __restrict__ Hxout, int Hxos,
                    float* __restrict__ Hyout, int Hyos)
{
    int b = blockIdx.z;
    E     += (size_t)b * Es;
    Hx    += (size_t)b * Hxs;
    Hy    += (size_t)b * Hys;
    Hxout += (size_t)b * Hxos;
    Hyout += (size_t)b * Hyos;

    float fl[12];
    #pragma unroll
    for (int k = 0; k < 12; k++) fl[k] = __ldg(F + k);

    int i  = blockIdx.y * blockDim.y + threadIdx.y;          // 0..1023 (guarded)
    int j0 = (blockIdx.x * blockDim.x + threadIdx.x) * 4;    // 0..1020

    if (i >= 2 && i <= 1020 && j0 >= 2 && j0 <= 1016) {
        #pragma unroll
        for (int u = 0; u < 4; u++) {
            int j = j0 + u;
            Hxout[i*1023 + j] = hx_pt<true>(E, Hx, fl, i, j);
            Hyout[i*1022 + j] = hy_pt<true>(E, Hy, fl, i, j);
        }
    } else if (i < 1023) {
        #pragma unroll
        for (int u = 0; u < 4; u++) {
            int j = j0 + u;
            if (i < 1022 && j < 1023) Hxout[i*1023 + j] = hx_pt<false>(E, Hx, fl, i, j);
            if (j < 1022)             Hyout[i*1022 + j] = hy_pt<false>(E, Hy, fl, i, j);
        }
    }
}

// ---------------------------------------------------------------------------
// Launch: 4 passes; intermediates (E_n, Hx_n, Hy_n) live directly in d_out.
// ---------------------------------------------------------------------------
extern "C" void kernel_launch(void* const* d_in, const int* in_sizes, int n_in,
                              void* d_out, int out_size)
{
    const float* E  = (const float*)d_in[0];   // (8,1024,1024,1)
    const float* Hx = (const float*)d_in[1];   // (8,1022,1023,1)
    const float* Hy = (const float*)d_in[2];   // (8,1023,1022,1)
    const float* F  = (const float*)d_in[3];   // (3,4,1,1)

    float* out   = (float*)d_out;
    const int B  = 8;
    float* outE  = out;                                   // 8 * 2048*1024
    float* outHx = outE  + (size_t)B * 2048 * 1024;       // 8 * 2044*1023
    float* outHy = outHx + (size_t)B * 2044 * 1023;       // 8 * 2046*1022

    const int Es   = 1024*1024, Hxs  = 1022*1023, Hys  = 1023*1022;
    const int Eos  = 2048*1024, Hxos = 2044*1023, Hyos = 2046*1022;

    dim3 blk(64, 4, 1);
    dim3 grd(4, 256, B);

    // Step 1
    amper_kernel<<<grd, blk>>>(E, Es, Hx, Hxs, Hy, Hys, F, outE, Eos);
    faraday_kernel<<<grd, blk>>>(outE, Eos, Hx, Hxs, Hy, Hys, F,
                                 outHx, Hxos, outHy, Hyos);
    // Step 2 (reads step-1 results from d_out)
    amper_kernel<<<grd, blk>>>(outE, Eos, outHx, Hxos, outHy, Hyos, F,
                               outE + 1024*1024, Eos);
    faraday_kernel<<<grd, blk>>>(outE + 1024*1024, Eos, outHx, Hxos, outHy, Hyos, F,
                                 outHx + 1022*1023, Hxos, outHy + 1023*1022, Hyos);
}

// round 11
// speedup vs baseline: 1.6694x; 1.6694x over previous
#include <cuda_runtime.h>

// FDTD 2-step update (Ampere + Faraday, 3rd-order one-sided boundary stencils)
// B=8, E:1024x1024, Hx:1022x1023, Hy:1023x1022.
// Outputs concat axis 1: E:(8,2048,1024)  Hx:(8,2044,1023)  Hy:(8,2046,1022)
// DT/DX = DT/(Z*DY) = 0.5 ; cf = [-11/6, 3, -3/2, 1/3]

#define CF0 (-11.0f/6.0f)
#define CF1 ( 3.0f)
#define CF2 (-1.5f)
#define CF3 ( 1.0f/3.0f)

// Combined (fwd+bwd) stencil coefficients, 0.5 folded in.
// Amper vertical Hy taps rows i-4..i+3 ; amper horizontal Hx taps cols j-4..j+3
#define W8_INIT  { -0.5f*CF3, -0.5f*CF2, -0.5f*CF1, -0.5f*CF0, 0.5f*CF0, 0.5f*CF1, 0.5f*CF2, 0.5f*CF3 }
#define HW8_INIT {  0.5f*CF3,  0.5f*CF2,  0.5f*CF1,  0.5f*CF0,-0.5f*CF0,-0.5f*CF1,-0.5f*CF2,-0.5f*CF3 }
// Faraday combined 6-tap (both hx horizontal, cols j-2..j+3, and hy vertical, rows i-2..i+3)
#define FX6_INIT { -0.5f*CF3, -0.5f*CF2, 0.5f*(CF0-CF1), 0.5f*(CF1-CF0), 0.5f*CF2, 0.5f*CF3 }

// ===========================================================================
// Per-point slow-path (boundary) functions — identical math to passing R4 code
// ===========================================================================
__device__ __forceinline__ float amper_pt_slow(
    const float* __restrict__ E, const float* __restrict__ Hx,
    const float* __restrict__ Hy, const float fl[12], int i, int j)
{
    float s = __ldg(E + i*1024 + j);
    if (i >= 2 && i <= 1021 && j >= 2 && j <= 1021) {
        float a1 = 0.f;
        #pragma unroll
        for (int a = 0; a < 4; a++)
            #pragma unroll
            for (int b = 0; b < 3; b++)
                a1 = fmaf(__ldg(Hy + (i-2+a)*1022 + (j-2+b)), fl[b*4+a], a1);
        float a2 = 0.f;
        #pragma unroll
        for (int a = 0; a < 3; a++)
            #pragma unroll
            for (int b = 0; b < 4; b++)
                a2 = fmaf(__ldg(Hx + (i-2+a)*1023 + (j-2+b)), fl[a*4+b], a2);
        s += 0.5f * (a1 - a2);
    }
    if (i <= 1019 && j >= 1 && j <= 1022) {
        const float* p = Hy + i*1022 + (j-1);
        s += 0.5f*(CF0*__ldg(p) + CF1*__ldg(p+1022) + CF2*__ldg(p+2044) + CF3*__ldg(p+3066));
    }
    if (i >= 4 && j >= 1 && j <= 1022) {
        const float* p = Hy + (i-4)*1022 + (j-1);
        s -= 0.5f*(CF3*__ldg(p) + CF2*__ldg(p+1022) + CF1*__ldg(p+2044) + CF0*__ldg(p+3066));
    }
    if (i >= 1 && i <= 1022 && j <= 1019) {
        const float* p = Hx + (i-1)*1023 + j;
        s -= 0.5f*(CF0*__ldg(p) + CF1*__ldg(p+1) + CF2*__ldg(p+2) + CF3*__ldg(p+3));
    }
    if (i >= 1 && i <= 1022 && j >= 4) {
        const float* p = Hx + (i-1)*1023 + (j-4);
        s += 0.5f*(CF3*__ldg(p) + CF2*__ldg(p+1) + CF1*__ldg(p+2) + CF0*__ldg(p+3));
    }
    return s;
}

__device__ __forceinline__ float hx_pt_slow(
    const float* __restrict__ E, const float* __restrict__ Hx,
    const float fl[12], int i, int j)
{
    float s3 = 0.f;
    if (j >= 1 && j <= 1021) {
        float a = 0.f;
        #pragma unroll
        for (int a2 = 0; a2 < 3; a2++)
            #pragma unroll
            for (int b = 0; b < 4; b++)
                a = fmaf(__ldg(E + (i+a2)*1024 + (j-1+b)), fl[a2*4+b], a);
        s3 += 0.5f * a;
    }
    if (j <= 1020) {
        const float* p = E + (i+1)*1024 + j;
        s3 += 0.5f*(CF0*__ldg(p) + CF1*__ldg(p+1) + CF2*__ldg(p+2) + CF3*__ldg(p+3));
    }
    if (j >= 2) {
        const float* p = E + (i+1)*1024 + (j-2);
        s3 -= 0.5f*(CF3*__ldg(p) + CF2*__ldg(p+1) + CF1*__ldg(p+2) + CF0*__ldg(p+3));
    }
    return __ldg(Hx + i*1023 + j) - s3;
}

__device__ __forceinline__ float hy_pt_slow(
    const float* __restrict__ E, const float* __restrict__ Hy,
    const float fl[12], int i, int j)
{
    float s4 = 0.f;
    if (i >= 1 && i <= 1021) {
        float a = 0.f;
        #pragma unroll
        for (int a2 = 0; a2 < 4; a2++)
            #pragma unroll
            for (int b = 0; b < 3; b++)
                a = fmaf(__ldg(E + (i-1+a2)*1024 + (j+b)), fl[b*4+a2], a);
        s4 += 0.5f * a;
    }
    if (i <= 1020) {
        const float* p = E + i*1024 + (j+1);
        s4 += 0.5f*(CF0*__ldg(p) + CF1*__ldg(p+1024) + CF2*__ldg(p+2048) + CF3*__ldg(p+3072));
    }
    if (i >= 2) {
        const float* p = E + (i-2)*1024 + (j+1);
        s4 -= 0.5f*(CF3*__ldg(p) + CF2*__ldg(p+1024) + CF1*__ldg(p+2048) + CF0*__ldg(p+3072));
    }
    return __ldg(Hy + i*1022 + j) + s4;
}

// ===========================================================================
// Ampere kernel: each thread computes an 8x4 tile of E_n.
// ===========================================================================
__global__ __launch_bounds__(256)
void amper_kernel(const float* __restrict__ E,  int Es,
                  const float* __restrict__ Hx, int Hxs,
                  const float* __restrict__ Hy, int Hys,
                  const float* __restrict__ F,
                  float* __restrict__ Eout, int Eos)
{
    const int b = blockIdx.z;
    E    += (size_t)b * Es;
    Hx   += (size_t)b * Hxs;
    Hy   += (size_t)b * Hys;
    Eout += (size_t)b * Eos;

    float fl05[12], fl[12];
    #pragma unroll
    for (int k = 0; k < 12; k++) { fl[k] = __ldg(F + k); fl05[k] = 0.5f * fl[k]; }

    const int j0 = (blockIdx.x * 32 + threadIdx.x) * 4;   // 0..1020
    const int i0 = (blockIdx.y * 8  + threadIdx.y) * 8;   // 0..1016

    if (i0 >= 8 && i0 <= 1008 && j0 >= 4 && j0 <= 1016) {
        const float W8[8]  = W8_INIT;
        const float HW8[8] = HW8_INIT;

        float acc[8][4];
        #pragma unroll
        for (int li = 0; li < 8; ++li) {
            float4 e = *reinterpret_cast<const float4*>(E + (i0+li)*1024 + j0);
            acc[li][0]=e.x; acc[li][1]=e.y; acc[li][2]=e.z; acc[li][3]=e.w;
        }

        // ---- Hy phase: stream 15 rows (i0-4 .. i0+10), cols j0-2..j0+3 ----
        #pragma unroll
        for (int t = 0; t < 15; ++t) {
            const float* hb = Hy + (i0 - 4 + t)*1022 + (j0 - 2);
            float2 v0 = *reinterpret_cast<const float2*>(hb);
            float2 v1 = *reinterpret_cast<const float2*>(hb + 2);
            float2 v2 = *reinterpret_cast<const float2*>(hb + 4);
            float h[6] = { v0.x, v0.y, v1.x, v1.y, v2.x, v2.y };
            #pragma unroll
            for (int li = 0; li < 8; ++li) {
                const int o = t - li;          // combined 8-tap vertical, col j-1
                if (o >= 0 && o < 8) {
                    #pragma unroll
                    for (int c = 0; c < 4; ++c)
                        acc[li][c] = fmaf(W8[o], h[c+1], acc[li][c]);
                }
                const int a = t - 2 - li;      // conv(Hy, f^T), added
                if (a >= 0 && a < 4) {
                    #pragma unroll
                    for (int bb = 0; bb < 3; ++bb)
                        #pragma unroll
                        for (int c = 0; c < 4; ++c)
                            acc[li][c] = fmaf(fl05[bb*4 + a], h[c+bb], acc[li][c]);
                }
            }
        }

        // ---- Hx phase: stream 10 rows (i0-2 .. i0+7), cols j0-4..j0+6 ----
        #pragma unroll
        for (int t = 0; t < 10; ++t) {
            const float* xb = Hx + (i0 - 2 + t)*1023 + (j0 - 4);
            float x[11];
            #pragma unroll
            for (int k = 0; k < 11; ++k) x[k] = __ldg(xb + k);
            {
                const int li = t - 1;          // combined 8-tap horizontal, row i-1
                if (li >= 0 && li < 8) {
                    #pragma unroll
                    for (int c = 0; c < 4; ++c)
                        #pragma unroll
                        for (int o = 0; o < 8; ++o)
                            acc[li][c] = fmaf(HW8[o], x[c+o], acc[li][c]);
                }
            }
            #pragma unroll
            for (int li = 0; li < 8; ++li) {
                const int a = t - li;          // conv(Hx, f), subtracted
                if (a >= 0 && a < 3) {
                    #pragma unroll
                    for (int bb = 0; bb < 4; ++bb)
                        #pragma unroll
                        for (int c = 0; c < 4; ++c)
                            acc[li][c] = fmaf(-fl05[a*4 + bb], x[c+2+bb], acc[li][c]);
                }
            }
        }

        #pragma unroll
        for (int li = 0; li < 8; ++li)
            *reinterpret_cast<float4*>(Eout + (i0+li)*1024 + j0) =
                make_float4(acc[li][0], acc[li][1], acc[li][2], acc[li][3]);
    } else {
        #pragma unroll
        for (int li = 0; li < 8; ++li)
            for (int c = 0; c < 4; ++c)
                Eout[(i0+li)*1024 + j0 + c] = amper_pt_slow(E, Hx, Hy, fl, i0+li, j0+c);
    }
}

// ===========================================================================
// Faraday kernel: each thread computes 8x4 tiles of Hx_n and Hy_n.
// ===========================================================================
__global__ __launch_bounds__(256)
void faraday_kernel(const float* __restrict__ E,  int Es,
                    const float* __restrict__ Hx, int Hxs,
                    const float* __restrict__ Hy, int Hys,
                    const float* __restrict__ F,
                    float* __restrict__ Hxout, int Hxos,
                    float* __restrict__ Hyout, int Hyos)
{
    const int b = blockIdx.z;
    E     += (size_t)b * Es;
    Hx    += (size_t)b * Hxs;
    Hy    += (size_t)b * Hys;
    Hxout += (size_t)b * Hxos;
    Hyout += (size_t)b * Hyos;

    float fl05[12], fl[12];
    #pragma unroll
    for (int k = 0; k < 12; k++) { fl[k] = __ldg(F + k); fl05[k] = 0.5f * fl[k]; }

    const int j0 = (blockIdx.x * 32 + threadIdx.x) * 4;   // 0..1020
    const int i0 = (blockIdx.y * 8  + threadIdx.y) * 8;   // 0..1016

    if (i0 >= 8 && i0 <= 1008 && j0 >= 4 && j0 <= 1016) {
        const float FX6[6] = FX6_INIT;

        // ---- Hx_n: stream E rows i0..i0+9, cols j0-4..j0+7 (3x float4) ----
        float ax[8][4];
        #pragma unroll
        for (int li = 0; li < 8; ++li)
            #pragma unroll
            for (int c = 0; c < 4; ++c)
                ax[li][c] = __ldg(Hx + (i0+li)*1023 + j0 + c);

        #pragma unroll
        for (int t = 0; t < 10; ++t) {
            const float* eb = E + (i0 + t)*1024 + (j0 - 4);
            float4 e0 = *reinterpret_cast<const float4*>(eb);
            float4 e1 = *reinterpret_cast<const float4*>(eb + 4);
            float4 e2 = *reinterpret_cast<const float4*>(eb + 8);
            float e[12] = { e0.x,e0.y,e0.z,e0.w, e1.x,e1.y,e1.z,e1.w, e2.x,e2.y,e2.z,e2.w };
            {
                const int li = t - 1;          // combined 6-tap horizontal on row i+1
                if (li >= 0 && li < 8) {
                    #pragma unroll
                    for (int c = 0; c < 4; ++c)
                        #pragma unroll
                        for (int o = 0; o < 6; ++o)
                            ax[li][c] = fmaf(-FX6[o], e[c+2+o], ax[li][c]);
                }
            }
            #pragma unroll
            for (int li = 0; li < 8; ++li) {
                const int a = t - li;          // conv(E, f), subtracted
                if (a >= 0 && a < 3) {
                    #pragma unroll
                    for (int bb = 0; bb < 4; ++bb)
                        #pragma unroll
                        for (int c = 0; c < 4; ++c)
                            ax[li][c] = fmaf(-fl05[a*4 + bb], e[c+3+bb], ax[li][c]);
                }
            }
        }
        #pragma unroll
        for (int li = 0; li < 8; ++li)
            #pragma unroll
            for (int c = 0; c < 4; ++c)
                Hxout[(i0+li)*1023 + j0 + c] = ax[li][c];

        // ---- Hy_n: stream E rows i0-2..i0+10, cols j0..j0+7 (2x float4) ----
        float ay[8][4];
        #pragma unroll
        for (int li = 0; li < 8; ++li) {
            const float* yb = Hy + (i0+li)*1022 + j0;
            float2 v0 = *reinterpret_cast<const float2*>(yb);
            float2 v1 = *reinterpret_cast<const float2*>(yb + 2);
            ay[li][0]=v0.x; ay[li][1]=v0.y; ay[li][2]=v1.x; ay[li][3]=v1.y;
        }

        #pragma unroll
        for (int t = 0; t < 13; ++t) {
            const float* eb = E + (i0 - 2 + t)*1024 + j0;
            float4 e0 = *reinterpret_cast<const float4*>(eb);
            float4 e1 = *reinterpret_cast<const float4*>(eb + 4);
            float e[8] = { e0.x,e0.y,e0.z,e0.w, e1.x,e1.y,e1.z,e1.w };
            #pragma unroll
            for (int li = 0; li < 8; ++li) {
                const int o = t - li;          // combined 6-tap vertical, col j+1
                if (o >= 0 && o < 6) {
                    #pragma unroll
                    for (int c = 0; c < 4; ++c)
                        ay[li][c] = fmaf(FX6[o], e[c+1], ay[li][c]);
                }
                const int a = t - 1 - li;      // conv(E, f^T), added
                if (a >= 0 && a < 4) {
                    #pragma unroll
                    for (int bb = 0; bb < 3; ++bb)
                        #pragma unroll
                        for (int c = 0; c < 4; ++c)
                            ay[li][c] = fmaf(fl05[bb*4 + a], e[c+bb], ay[li][c]);
                }
            }
        }
        #pragma unroll
        for (int li = 0; li < 8; ++li) {
            float* yo = Hyout + (i0+li)*1022 + j0;
            *reinterpret_cast<float2*>(yo)     = make_float2(ay[li][0], ay[li][1]);
            *reinterpret_cast<float2*>(yo + 2) = make_float2(ay[li][2], ay[li][3]);
        }
    } else {
        #pragma unroll
        for (int li = 0; li < 8; ++li) {
            const int i = i0 + li;
            for (int c = 0; c < 4; ++c) {
                const int j = j0 + c;
                if (i < 1022 && j < 1023) Hxout[i*1023 + j] = hx_pt_slow(E, Hx, fl, i, j);
                if (i < 1023 && j < 1022) Hyout[i*1022 + j] = hy_pt_slow(E, Hy, fl, i, j);
            }
        }
    }
}

// ---------------------------------------------------------------------------
// Launch: 4 passes; intermediates (E_n, Hx_n, Hy_n) live directly in d_out.
// ---------------------------------------------------------------------------
extern "C" void kernel_launch(void* const* d_in, const int* in_sizes, int n_in,
                              void* d_out, int out_size)
{
    const float* E  = (const float*)d_in[0];   // (8,1024,1024,1)
    const float* Hx = (const float*)d_in[1];   // (8,1022,1023,1)
    const float* Hy = (const float*)d_in[2];   // (8,1023,1022,1)
    const float* F  = (const float*)d_in[3];   // (3,4,1,1)

    float* out   = (float*)d_out;
    const int B  = 8;
    float* outE  = out;                                   // 8 * 2048*1024
    float* outHx = outE  + (size_t)B * 2048 * 1024;       // 8 * 2044*1023
    float* outHy = outHx + (size_t)B * 2044 * 1023;       // 8 * 2046*1022

    const int Es   = 1024*1024, Hxs  = 1022*1023, Hys  = 1023*1022;
    const int Eos  = 2048*1024, Hxos = 2044*1023, Hyos = 2046*1022;

    dim3 blk(32, 8, 1);
    dim3 grd(8, 16, B);

    // Step 1
    amper_kernel<<<grd, blk>>>(E, Es, Hx, Hxs, Hy, Hys, F, outE, Eos);
    faraday_kernel<<<grd, blk>>>(outE, Eos, Hx, Hxs, Hy, Hys, F,
                                 outHx, Hxos, outHy, Hyos);
    // Step 2 (reads step-1 results from d_out)
    amper_kernel<<<grd, blk>>>(outE, Eos, outHx, Hxos, outHy, Hyos, F,
                               outE + 1024*1024, Eos);
    faraday_kernel<<<grd, blk>>>(outE + 1024*1024, Eos, outHx, Hxos, outHy, Hyos, F,
                                 outHx + 1022*1023, Hxos, outHy + 1023*1022, Hyos);
}